// round 1
// baseline (speedup 1.0000x reference)
#include <cuda_runtime.h>
#include <cuda_bf16.h>
#include <cstdint>

#define NROWS 16384
#define DIM   256
#define BM    128
#define BN    128
#define PAD   8
#define LDS   (DIM + PAD)          // 264 bf16 per smem row (528B, 33*16B -> conflict-free ldmatrix)
#define KAPPA 5.0f
#define SMEM_BYTES ((BM + BN) * LDS * 2)   // 135168

// Scratch (device globals; no allocations allowed)
__device__ __nv_bfloat16 g_xn[NROWS * DIM];   // normalized rows, bf16
__device__ float         g_density[NROWS];

static __device__ __forceinline__ uint32_t pack_bf2(float a, float b) {
    __nv_bfloat162 h = __floats2bfloat162_rn(a, b);
    return *reinterpret_cast<uint32_t*>(&h);
}

// ---------------- Phase 1: L2-normalize rows, write bf16 ----------------
__global__ void normalize_kernel(const float* __restrict__ x) {
    int gwarp = (blockIdx.x * blockDim.x + threadIdx.x) >> 5;
    int lane  = threadIdx.x & 31;
    if (gwarp >= NROWS) return;
    const float4* p = reinterpret_cast<const float4*>(x + (size_t)gwarp * DIM);
    float4 v0 = p[lane * 2 + 0];
    float4 v1 = p[lane * 2 + 1];
    float ss = v0.x*v0.x + v0.y*v0.y + v0.z*v0.z + v0.w*v0.w
             + v1.x*v1.x + v1.y*v1.y + v1.z*v1.z + v1.w*v1.w;
    #pragma unroll
    for (int o = 16; o; o >>= 1) ss += __shfl_xor_sync(0xffffffffu, ss, o);
    float inv = 1.0f / fmaxf(sqrtf(ss), 1e-12f);

    uint4 out;
    out.x = pack_bf2(v0.x * inv, v0.y * inv);
    out.y = pack_bf2(v0.z * inv, v0.w * inv);
    out.z = pack_bf2(v1.x * inv, v1.y * inv);
    out.w = pack_bf2(v1.z * inv, v1.w * inv);
    reinterpret_cast<uint4*>(g_xn)[gwarp * (DIM / 8) + lane] = out;
}

// ---------------- mma / ldmatrix helpers ----------------
static __device__ __forceinline__ void ldsm_x4(uint32_t* r, uint32_t addr) {
    asm volatile("ldmatrix.sync.aligned.m8n8.x4.shared.b16 {%0,%1,%2,%3}, [%4];\n"
                 : "=r"(r[0]), "=r"(r[1]), "=r"(r[2]), "=r"(r[3]) : "r"(addr));
}
static __device__ __forceinline__ void mma16816(float* c, const uint32_t* a, const uint32_t* b) {
    asm volatile("mma.sync.aligned.m16n8k16.row.col.f32.bf16.bf16.f32 "
                 "{%0,%1,%2,%3}, {%4,%5,%6,%7}, {%8,%9}, {%0,%1,%2,%3};\n"
                 : "+f"(c[0]), "+f"(c[1]), "+f"(c[2]), "+f"(c[3])
                 : "r"(a[0]), "r"(a[1]), "r"(a[2]), "r"(a[3]),
                   "r"(b[0]), "r"(b[1]));
}

// ---------------- Phase 2: fused sim GEMM + exp + row-sum ----------------
// 128 blocks; block b owns rows [b*128, b*128+128), loops over all 128 col tiles.
__global__ void __launch_bounds__(256, 1) kde_gemm_kernel() {
    extern __shared__ __nv_bfloat16 sm[];
    __nv_bfloat16* As = sm;                 // BM x LDS
    __nv_bfloat16* Bs = sm + BM * LDS;      // BN x LDS
    __shared__ float rowred[BM * 2];

    int tid  = threadIdx.x;
    int wid  = tid >> 5;
    int lane = tid & 31;
    int warp_m = wid & 3;       // 0..3 -> 32 rows each
    int warp_n = wid >> 2;      // 0..1 -> 64 cols each
    int row_base = blockIdx.x * BM;

    const uint4* gx = reinterpret_cast<const uint4*>(g_xn);  // 32 uint4 per row

    // Load A tile (128 rows x 256 bf16) once
    #pragma unroll
    for (int it = 0; it < 16; ++it) {
        int id = it * 256 + tid;
        int r = id >> 5, c = id & 31;
        reinterpret_cast<uint4*>(As + r * LDS)[c] = gx[(row_base + r) * 32 + c];
    }

    uint32_t As_base = (uint32_t)__cvta_generic_to_shared(As);
    uint32_t Bs_base = (uint32_t)__cvta_generic_to_shared(Bs);

    // ldmatrix lane addressing (bytes)
    int a_row = lane & 15;
    int a_col = ((lane >> 4) << 3);
    int b_row = (lane & 7) + ((lane >> 4) << 3);
    int b_col = (((lane >> 3) & 1) << 3);

    float acc[2][2] = {{0.f, 0.f}, {0.f, 0.f}};   // [m_frag][row_half(+0/+8)]

    for (int jt = 0; jt < NROWS / BN; ++jt) {
        __syncthreads();   // previous tile's consumers done with Bs
        #pragma unroll
        for (int it = 0; it < 16; ++it) {
            int id = it * 256 + tid;
            int r = id >> 5, c = id & 31;
            reinterpret_cast<uint4*>(Bs + r * LDS)[c] = gx[(jt * BN + r) * 32 + c];
        }
        __syncthreads();

        float cfr[2][8][4];
        #pragma unroll
        for (int mf = 0; mf < 2; ++mf)
            #pragma unroll
            for (int nf = 0; nf < 8; ++nf)
                #pragma unroll
                for (int e = 0; e < 4; ++e) cfr[mf][nf][e] = 0.f;

        #pragma unroll
        for (int ks = 0; ks < 16; ++ks) {
            int k0 = ks * 16;
            uint32_t a[2][4];
            #pragma unroll
            for (int mf = 0; mf < 2; ++mf) {
                int r = warp_m * 32 + mf * 16 + a_row;
                ldsm_x4(a[mf], As_base + (uint32_t)((r * LDS + k0 + a_col) * 2));
            }
            uint32_t b[8][2];
            #pragma unroll
            for (int p = 0; p < 4; ++p) {
                uint32_t t[4];
                int r = warp_n * 64 + p * 16 + b_row;
                ldsm_x4(t, Bs_base + (uint32_t)((r * LDS + k0 + b_col) * 2));
                b[2*p][0]   = t[0]; b[2*p][1]   = t[1];
                b[2*p+1][0] = t[2]; b[2*p+1][1] = t[3];
            }
            #pragma unroll
            for (int mf = 0; mf < 2; ++mf)
                #pragma unroll
                for (int nf = 0; nf < 8; ++nf)
                    mma16816(cfr[mf][nf], a[mf], b[nf]);
        }

        // epilogue: exp + accumulate row sums
        #pragma unroll
        for (int mf = 0; mf < 2; ++mf)
            #pragma unroll
            for (int nf = 0; nf < 8; ++nf) {
                acc[mf][0] += __expf(KAPPA * cfr[mf][nf][0]);
                acc[mf][0] += __expf(KAPPA * cfr[mf][nf][1]);
                acc[mf][1] += __expf(KAPPA * cfr[mf][nf][2]);
                acc[mf][1] += __expf(KAPPA * cfr[mf][nf][3]);
            }
    }

    // Reduce: 4 lanes per row group (lane%4), then across warp_n (2 warps)
    #pragma unroll
    for (int mf = 0; mf < 2; ++mf)
        #pragma unroll
        for (int rp = 0; rp < 2; ++rp) {
            float s = acc[mf][rp];
            s += __shfl_xor_sync(0xffffffffu, s, 1);
            s += __shfl_xor_sync(0xffffffffu, s, 2);
            if ((lane & 3) == 0) {
                int rl = warp_m * 32 + mf * 16 + rp * 8 + (lane >> 2);
                rowred[rl * 2 + warp_n] = s;
            }
        }
    __syncthreads();
    if (tid < BM)
        g_density[row_base + tid] = rowred[tid * 2] + rowred[tid * 2 + 1];
}

// ---------------- Phase 3: entropy = -mean(log(density + 1e-9)) ----------------
__global__ void entropy_kernel(float* __restrict__ out) {
    __shared__ float red[1024];
    int t = threadIdx.x;
    float s = 0.f;
    for (int i = t; i < NROWS; i += 1024)
        s += logf(g_density[i] + 1e-9f);
    red[t] = s;
    __syncthreads();
    #pragma unroll
    for (int o = 512; o; o >>= 1) {
        if (t < o) red[t] += red[t + o];
        __syncthreads();
    }
    if (t == 0) out[0] = -red[0] / (float)NROWS;
}

// ---------------- launch ----------------
extern "C" void kernel_launch(void* const* d_in, const int* in_sizes, int n_in,
                              void* d_out, int out_size) {
    (void)in_sizes; (void)n_in; (void)out_size;
    const float* x = (const float*)d_in[0];
    float* out = (float*)d_out;

    cudaFuncSetAttribute(kde_gemm_kernel,
                         cudaFuncAttributeMaxDynamicSharedMemorySize, SMEM_BYTES);

    normalize_kernel<<<NROWS / 8, 256>>>(x);          // 8 warps (rows) per block
    kde_gemm_kernel<<<NROWS / BM, 256, SMEM_BYTES>>>();
    entropy_kernel<<<1, 1024>>>(out);
}

// round 3
// speedup vs baseline: 1.2633x; 1.2633x over previous
#include <cuda_runtime.h>
#include <cuda_bf16.h>
#include <cstdint>

#define NROWS 16384
#define DIM   256
#define NT    (NROWS / 128)        // 128 tiles per side
#define PAD   8
#define LDS   (DIM + PAD)          // 264 bf16 per smem row -> conflict-free ldmatrix
#define KAPPA 5.0f
#define TILE_SM_BYTES (128 * LDS * 2)
#define SMEM_BYTES (2 * TILE_SM_BYTES)   // 135168

// Scratch (device globals; no allocations allowed)
__device__ __nv_bfloat16 g_xn[NROWS * DIM];   // normalized rows, bf16
__device__ float         g_density[NROWS];

static __device__ __forceinline__ uint32_t pack_bf2(float a, float b) {
    __nv_bfloat162 h = __floats2bfloat162_rn(a, b);
    return *reinterpret_cast<uint32_t*>(&h);
}

// ---------------- Phase 1: L2-normalize rows -> bf16; zero g_density ----------------
__global__ void normalize_kernel(const float* __restrict__ x) {
    int gwarp = (blockIdx.x * blockDim.x + threadIdx.x) >> 5;
    int lane  = threadIdx.x & 31;
    if (gwarp >= NROWS) return;
    const float4* p = reinterpret_cast<const float4*>(x + (size_t)gwarp * DIM);
    float4 v0 = p[lane * 2 + 0];
    float4 v1 = p[lane * 2 + 1];
    float ss = v0.x*v0.x + v0.y*v0.y + v0.z*v0.z + v0.w*v0.w
             + v1.x*v1.x + v1.y*v1.y + v1.z*v1.z + v1.w*v1.w;
    #pragma unroll
    for (int o = 16; o; o >>= 1) ss += __shfl_xor_sync(0xffffffffu, ss, o);
    float inv = 1.0f / fmaxf(sqrtf(ss), 1e-12f);

    uint4 out;
    out.x = pack_bf2(v0.x * inv, v0.y * inv);
    out.y = pack_bf2(v0.z * inv, v0.w * inv);
    out.z = pack_bf2(v1.x * inv, v1.y * inv);
    out.w = pack_bf2(v1.z * inv, v1.w * inv);
    reinterpret_cast<uint4*>(g_xn)[gwarp * (DIM / 8) + lane] = out;
    if (lane == 0) g_density[gwarp] = 0.0f;   // zero accumulator for atomics
}

// ---------------- mma / ldmatrix / cp.async helpers ----------------
static __device__ __forceinline__ void ldsm_x4(uint32_t* r, uint32_t addr) {
    asm volatile("ldmatrix.sync.aligned.m8n8.x4.shared.b16 {%0,%1,%2,%3}, [%4];\n"
                 : "=r"(r[0]), "=r"(r[1]), "=r"(r[2]), "=r"(r[3]) : "r"(addr));
}
static __device__ __forceinline__ void mma16816(float* c, const uint32_t* a, const uint32_t* b) {
    asm volatile("mma.sync.aligned.m16n8k16.row.col.f32.bf16.bf16.f32 "
                 "{%0,%1,%2,%3}, {%4,%5,%6,%7}, {%8,%9}, {%0,%1,%2,%3};\n"
                 : "+f"(c[0]), "+f"(c[1]), "+f"(c[2]), "+f"(c[3])
                 : "r"(a[0]), "r"(a[1]), "r"(a[2]), "r"(a[3]),
                   "r"(b[0]), "r"(b[1]));
}
#define CP_ASYNC16(dst, src) \
    asm volatile("cp.async.cg.shared.global [%0], [%1], 16;" :: "r"(dst), "l"(src) : "memory")
#define CP_COMMIT()  asm volatile("cp.async.commit_group;" ::: "memory")
#define CP_WAIT(n)   asm volatile("cp.async.wait_group %0;" :: "n"(n) : "memory")

// ---------------- Phase 2: symmetric fused sim GEMM + exp + row/col sums ----------------
// grid (NT, NT); block (ti,tj) with ti<=tj computes one 128x128 sim tile:
//  - row sums of exp(5*sim) -> atomicAdd into g_density[ti*128 ..]
//  - col sums (if ti<tj)    -> atomicAdd into g_density[tj*128 ..]
__global__ void __launch_bounds__(256, 1) kde_sym_kernel() {
    int ti = blockIdx.x, tj = blockIdx.y;
    if (ti > tj) return;
    bool diag = (ti == tj);

    extern __shared__ __nv_bfloat16 sm[];
    __nv_bfloat16* As = sm;                   // 128 x LDS
    __nv_bfloat16* Bs = sm + 128 * LDS;       // 128 x LDS
    __shared__ float scol[128];

    int tid  = threadIdx.x;
    int wid  = tid >> 5;
    int lane = tid & 31;
    int warp_m = wid & 3;        // 32 rows each
    int warp_n = wid >> 2;       // 64 cols each

    if (tid < 128) scol[tid] = 0.0f;

    uint32_t As_base = (uint32_t)__cvta_generic_to_shared(As);
    uint32_t Bs_base = (uint32_t)__cvta_generic_to_shared(Bs);

    // ---- issue loads: 4 K-chunks (64 cols = 128B each), A+B per commit group ----
    // per chunk per tile: 128 rows x 8 (16B units) = 1024 ops -> 4 per thread
    #pragma unroll
    for (int g = 0; g < 4; ++g) {
        #pragma unroll
        for (int i = 0; i < 4; ++i) {
            int id = i * 256 + tid;
            int r = id >> 3, u = id & 7;
            uint32_t off = (uint32_t)(r * (LDS * 2) + g * 128 + u * 16);
            const char* srcA = (const char*)g_xn + ((size_t)(ti * 128 + r) * DIM + g * 64 + u * 8) * 2;
            CP_ASYNC16(As_base + off, srcA);
            const char* srcB = (const char*)g_xn + ((size_t)(tj * 128 + r) * DIM + g * 64 + u * 8) * 2;
            CP_ASYNC16(Bs_base + off, srcB);
        }
        CP_COMMIT();
    }

    // ldmatrix lane addressing
    int a_row = lane & 15;
    int a_col = ((lane >> 4) << 3);
    int b_row = (lane & 7) + ((lane >> 4) << 3);
    int b_col = (((lane >> 3) & 1) << 3);

    float cfr[2][8][4];
    #pragma unroll
    for (int mf = 0; mf < 2; ++mf)
        #pragma unroll
        for (int nf = 0; nf < 8; ++nf)
            #pragma unroll
            for (int e = 0; e < 4; ++e) cfr[mf][nf][e] = 0.f;

    // ---- compute, consuming chunks progressively ----
    #pragma unroll
    for (int g = 0; g < 4; ++g) {
        if (g == 0)      CP_WAIT(3);
        else if (g == 1) CP_WAIT(2);
        else if (g == 2) CP_WAIT(1);
        else             CP_WAIT(0);
        __syncthreads();

        #pragma unroll
        for (int ks = 0; ks < 4; ++ks) {
            int k0 = g * 64 + ks * 16;
            uint32_t a[2][4];
            #pragma unroll
            for (int mf = 0; mf < 2; ++mf) {
                int r = warp_m * 32 + mf * 16 + a_row;
                ldsm_x4(a[mf], As_base + (uint32_t)((r * LDS + k0 + a_col) * 2));
            }
            uint32_t b[8][2];
            #pragma unroll
            for (int p = 0; p < 4; ++p) {
                uint32_t t[4];
                int r = warp_n * 64 + p * 16 + b_row;
                ldsm_x4(t, Bs_base + (uint32_t)((r * LDS + k0 + b_col) * 2));
                b[2*p][0]   = t[0]; b[2*p][1]   = t[1];
                b[2*p+1][0] = t[2]; b[2*p+1][1] = t[3];
            }
            #pragma unroll
            for (int mf = 0; mf < 2; ++mf)
                #pragma unroll
                for (int nf = 0; nf < 8; ++nf)
                    mma16816(cfr[mf][nf], a[mf], b[nf]);
        }
    }

    // ---- epilogue: exp, row sums + col sums ----
    float rowacc[2][2] = {{0.f,0.f},{0.f,0.f}};
    float colacc[8][2];
    #pragma unroll
    for (int nf = 0; nf < 8; ++nf) { colacc[nf][0] = 0.f; colacc[nf][1] = 0.f; }

    #pragma unroll
    for (int mf = 0; mf < 2; ++mf)
        #pragma unroll
        for (int nf = 0; nf < 8; ++nf) {
            float e0 = __expf(KAPPA * cfr[mf][nf][0]);
            float e1 = __expf(KAPPA * cfr[mf][nf][1]);
            float e2 = __expf(KAPPA * cfr[mf][nf][2]);
            float e3 = __expf(KAPPA * cfr[mf][nf][3]);
            rowacc[mf][0] += e0 + e1;
            rowacc[mf][1] += e2 + e3;
            colacc[nf][0] += e0 + e2;
            colacc[nf][1] += e1 + e3;
        }

    // row sums: reduce over lane&3, atomicAdd (both warp_n halves add)
    #pragma unroll
    for (int mf = 0; mf < 2; ++mf)
        #pragma unroll
        for (int rp = 0; rp < 2; ++rp) {
            float s = rowacc[mf][rp];
            s += __shfl_xor_sync(0xffffffffu, s, 1);
            s += __shfl_xor_sync(0xffffffffu, s, 2);
            if ((lane & 3) == 0) {
                int row = ti * 128 + warp_m * 32 + mf * 16 + rp * 8 + (lane >> 2);
                atomicAdd(&g_density[row], s);
            }
        }

    // col sums (only off-diagonal): reduce over lane>>2, combine warp_m via smem atomics
    if (!diag) {
        #pragma unroll
        for (int nf = 0; nf < 8; ++nf)
            #pragma unroll
            for (int h = 0; h < 2; ++h) {
                float s = colacc[nf][h];
                s += __shfl_xor_sync(0xffffffffu, s, 4);
                s += __shfl_xor_sync(0xffffffffu, s, 8);
                s += __shfl_xor_sync(0xffffffffu, s, 16);
                if (lane < 4)
                    atomicAdd(&scol[warp_n * 64 + nf * 8 + 2 * lane + h], s);
            }
        __syncthreads();
        if (tid < 128)
            atomicAdd(&g_density[tj * 128 + tid], scol[tid]);
    }
}

// ---------------- Phase 3: entropy = -mean(log(density + 1e-9)) ----------------
__global__ void entropy_kernel(float* __restrict__ out) {
    __shared__ float red[1024];
    int t = threadIdx.x;
    float s = 0.f;
    for (int i = t; i < NROWS; i += 1024)
        s += logf(g_density[i] + 1e-9f);
    red[t] = s;
    __syncthreads();
    #pragma unroll
    for (int o = 512; o; o >>= 1) {
        if (t < o) red[t] += red[t + o];
        __syncthreads();
    }
    if (t == 0) out[0] = -red[0] / (float)NROWS;
}

// ---------------- launch ----------------
extern "C" void kernel_launch(void* const* d_in, const int* in_sizes, int n_in,
                              void* d_out, int out_size) {
    (void)in_sizes; (void)n_in; (void)out_size;
    const float* x = (const float*)d_in[0];
    float* out = (float*)d_out;

    cudaFuncSetAttribute(kde_sym_kernel,
                         cudaFuncAttributeMaxDynamicSharedMemorySize, SMEM_BYTES);

    normalize_kernel<<<NROWS / 8, 256>>>(x);
    dim3 grid(NT, NT);
    kde_sym_kernel<<<grid, 256, SMEM_BYTES>>>();
    entropy_kernel<<<1, 1024>>>(out);
}

// round 4
// speedup vs baseline: 1.4931x; 1.1819x over previous
#include <cuda_runtime.h>
#include <cuda_bf16.h>
#include <cstdint>

#define NROWS 16384
#define DIM   256
#define NT    (NROWS / 128)        // 128 tiles per side
#define PAD   8
#define LDS   (DIM + PAD)          // 264 bf16/row -> conflict-free ldmatrix
#define KAPPA 5.0f
#define TILE_SM_BYTES (128 * LDS * 2)            // 67584
#define SMEM_BYTES (3 * TILE_SM_BYTES)           // A + 2x B = 202752

// Scratch (device globals; no allocations allowed)
__device__ __nv_bfloat16 g_xn[NROWS * DIM];
__device__ float         g_density[NROWS];

static __device__ __forceinline__ uint32_t pack_bf2(float a, float b) {
    __nv_bfloat162 h = __floats2bfloat162_rn(a, b);
    return *reinterpret_cast<uint32_t*>(&h);
}

// ---------------- Phase 1: L2-normalize rows -> bf16; zero g_density ----------------
__global__ void normalize_kernel(const float* __restrict__ x) {
    int gwarp = (blockIdx.x * blockDim.x + threadIdx.x) >> 5;
    int lane  = threadIdx.x & 31;
    if (gwarp >= NROWS) return;
    const float4* p = reinterpret_cast<const float4*>(x + (size_t)gwarp * DIM);
    float4 v0 = p[lane * 2 + 0];
    float4 v1 = p[lane * 2 + 1];
    float ss = v0.x*v0.x + v0.y*v0.y + v0.z*v0.z + v0.w*v0.w
             + v1.x*v1.x + v1.y*v1.y + v1.z*v1.z + v1.w*v1.w;
    #pragma unroll
    for (int o = 16; o; o >>= 1) ss += __shfl_xor_sync(0xffffffffu, ss, o);
    float inv = 1.0f / fmaxf(sqrtf(ss), 1e-12f);

    uint4 out;
    out.x = pack_bf2(v0.x * inv, v0.y * inv);
    out.y = pack_bf2(v0.z * inv, v0.w * inv);
    out.z = pack_bf2(v1.x * inv, v1.y * inv);
    out.w = pack_bf2(v1.z * inv, v1.w * inv);
    reinterpret_cast<uint4*>(g_xn)[gwarp * (DIM / 8) + lane] = out;
    if (lane == 0) g_density[gwarp] = 0.0f;
}

// ---------------- helpers ----------------
static __device__ __forceinline__ void ldsm_x4(uint32_t* r, uint32_t addr) {
    asm volatile("ldmatrix.sync.aligned.m8n8.x4.shared.b16 {%0,%1,%2,%3}, [%4];\n"
                 : "=r"(r[0]), "=r"(r[1]), "=r"(r[2]), "=r"(r[3]) : "r"(addr));
}
static __device__ __forceinline__ void mma16816(float* c, const uint32_t* a, const uint32_t* b) {
    asm volatile("mma.sync.aligned.m16n8k16.row.col.f32.bf16.bf16.f32 "
                 "{%0,%1,%2,%3}, {%4,%5,%6,%7}, {%8,%9}, {%0,%1,%2,%3};\n"
                 : "+f"(c[0]), "+f"(c[1]), "+f"(c[2]), "+f"(c[3])
                 : "r"(a[0]), "r"(a[1]), "r"(a[2]), "r"(a[3]),
                   "r"(b[0]), "r"(b[1]));
}
#define CP_ASYNC16(dst, src) \
    asm volatile("cp.async.cg.shared.global [%0], [%1], 16;" :: "r"(dst), "l"(src) : "memory")
#define CP_COMMIT()  asm volatile("cp.async.commit_group;" ::: "memory")
#define CP_WAIT0()   asm volatile("cp.async.wait_group 0;" :: : "memory")

// issue a full 128x256 bf16 tile load (4096 x 16B, 16 per thread)
static __device__ __forceinline__ void load_tile(uint32_t dst_base, int grow0, int tid) {
    #pragma unroll
    for (int i = 0; i < 16; ++i) {
        int id = i * 256 + tid;
        int r = id >> 5, u = id & 31;
        uint32_t dst = dst_base + (uint32_t)(r * (LDS * 2) + u * 16);
        const char* src = (const char*)g_xn + ((size_t)(grow0 + r) * DIM + u * 8) * 2;
        CP_ASYNC16(dst, src);
    }
}

static __device__ __forceinline__ void tile_of(int q, int p, int& ti, int& tj) {
    int seg1 = NT - p;
    if (q < seg1) { ti = p;          tj = p + q; }
    else          { ti = NT - 1 - p; tj = NT - 1 - p + (q - seg1); }
}

// ---------------- Phase 2: persistent pair-scheduled symmetric fused GEMM ----------------
// 128 CTAs; pair p = b>>1 owns row-panels {p, 127-p} (129 tiles), half b&1 takes 65/64.
__global__ void __launch_bounds__(256, 1) kde_sym_kernel() {
    extern __shared__ __nv_bfloat16 sm[];
    uint32_t A_sm = (uint32_t)__cvta_generic_to_shared(sm);
    uint32_t B_sm = A_sm + TILE_SM_BYTES;

    int tid  = threadIdx.x;
    int lane = tid & 31;
    int wid  = tid >> 5;
    int warp_m = wid & 3;        // 32 rows each
    int warp_n = wid >> 2;       // 64 cols each

    int p = blockIdx.x >> 1;
    int h = blockIdx.x & 1;
    int qbeg = h ? 65 : 0;
    int qend = h ? 129 : 65;

    // ldmatrix lane addressing
    int a_row = lane & 15;
    int a_col = ((lane >> 4) << 3);
    int b_row = (lane & 7) + ((lane >> 4) << 3);
    int b_col = (((lane >> 3) & 1) << 3);

    int ti, tj;
    tile_of(qbeg, p, ti, tj);
    int cur_ti = ti;

    // prologue: A panel + first B tile
    load_tile(A_sm, ti * 128, tid);
    load_tile(B_sm, tj * 128, tid);
    CP_COMMIT();
    CP_WAIT0();
    __syncthreads();

    float rowacc[2][2] = {{0.f,0.f},{0.f,0.f}};
    int cur = 0;

    for (int q = qbeg; q < qend; ++q) {
        tile_of(q, p, ti, tj);
        bool diag = (ti == tj);

        // prefetch next B tile into other buffer
        int qn = q + 1;
        int nti = 0, ntj = 0;
        if (qn < qend) {
            tile_of(qn, p, nti, ntj);
            load_tile(B_sm + (cur ^ 1) * TILE_SM_BYTES, ntj * 128, tid);
            CP_COMMIT();
        }

        // ---- 16-kstep MMA mainloop on resident tiles ----
        float cfr[2][8][4];
        #pragma unroll
        for (int mf = 0; mf < 2; ++mf)
            #pragma unroll
            for (int nf = 0; nf < 8; ++nf)
                #pragma unroll
                for (int e = 0; e < 4; ++e) cfr[mf][nf][e] = 0.f;

        uint32_t Bb = B_sm + cur * TILE_SM_BYTES;
        #pragma unroll
        for (int ks = 0; ks < 16; ++ks) {
            int k0 = ks * 16;
            uint32_t a[2][4];
            #pragma unroll
            for (int mf = 0; mf < 2; ++mf) {
                int r = warp_m * 32 + mf * 16 + a_row;
                ldsm_x4(a[mf], A_sm + (uint32_t)((r * LDS + k0 + a_col) * 2));
            }
            uint32_t bfr[8][2];
            #pragma unroll
            for (int pp = 0; pp < 4; ++pp) {
                uint32_t t[4];
                int r = warp_n * 64 + pp * 16 + b_row;
                ldsm_x4(t, Bb + (uint32_t)((r * LDS + k0 + b_col) * 2));
                bfr[2*pp][0]   = t[0]; bfr[2*pp][1]   = t[1];
                bfr[2*pp+1][0] = t[2]; bfr[2*pp+1][1] = t[3];
            }
            #pragma unroll
            for (int mf = 0; mf < 2; ++mf)
                #pragma unroll
                for (int nf = 0; nf < 8; ++nf)
                    mma16816(cfr[mf][nf], a[mf], bfr[nf]);
        }

        // ---- epilogue: exp, accumulate row sums (regs) + col sums (global atomics) ----
        float colacc[8][2];
        #pragma unroll
        for (int nf = 0; nf < 8; ++nf) { colacc[nf][0] = 0.f; colacc[nf][1] = 0.f; }

        #pragma unroll
        for (int mf = 0; mf < 2; ++mf)
            #pragma unroll
            for (int nf = 0; nf < 8; ++nf) {
                float e0 = __expf(KAPPA * cfr[mf][nf][0]);
                float e1 = __expf(KAPPA * cfr[mf][nf][1]);
                float e2 = __expf(KAPPA * cfr[mf][nf][2]);
                float e3 = __expf(KAPPA * cfr[mf][nf][3]);
                rowacc[mf][0] += e0 + e1;
                rowacc[mf][1] += e2 + e3;
                colacc[nf][0] += e0 + e2;
                colacc[nf][1] += e1 + e3;
            }

        if (!diag) {
            #pragma unroll
            for (int nf = 0; nf < 8; ++nf)
                #pragma unroll
                for (int hh = 0; hh < 2; ++hh) {
                    float s = colacc[nf][hh];
                    s += __shfl_xor_sync(0xffffffffu, s, 4);
                    s += __shfl_xor_sync(0xffffffffu, s, 8);
                    s += __shfl_xor_sync(0xffffffffu, s, 16);
                    if (lane < 4)
                        atomicAdd(&g_density[tj * 128 + warp_n * 64 + nf * 8 + 2 * lane + hh], s);
                }
        }

        // ---- buffer swap / A-panel boundary ----
        if (qn < qend && nti != cur_ti) {
            // flush row sums for finished panel
            #pragma unroll
            for (int mf = 0; mf < 2; ++mf)
                #pragma unroll
                for (int rp = 0; rp < 2; ++rp) {
                    float s = rowacc[mf][rp];
                    s += __shfl_xor_sync(0xffffffffu, s, 1);
                    s += __shfl_xor_sync(0xffffffffu, s, 2);
                    if ((lane & 3) == 0)
                        atomicAdd(&g_density[cur_ti * 128 + warp_m * 32 + mf * 16 + rp * 8 + (lane >> 2)], s);
                    rowacc[mf][rp] = 0.f;
                }
            CP_WAIT0();
            __syncthreads();              // everyone done with A before overwrite
            load_tile(A_sm, nti * 128, tid);
            CP_COMMIT();
            CP_WAIT0();
            __syncthreads();
            cur_ti = nti;
        } else {
            CP_WAIT0();                   // next B resident
            __syncthreads();              // all warps done reading buf[cur]
        }
        cur ^= 1;
    }

    // final row-sum flush
    #pragma unroll
    for (int mf = 0; mf < 2; ++mf)
        #pragma unroll
        for (int rp = 0; rp < 2; ++rp) {
            float s = rowacc[mf][rp];
            s += __shfl_xor_sync(0xffffffffu, s, 1);
            s += __shfl_xor_sync(0xffffffffu, s, 2);
            if ((lane & 3) == 0)
                atomicAdd(&g_density[cur_ti * 128 + warp_m * 32 + mf * 16 + rp * 8 + (lane >> 2)], s);
        }
}

// ---------------- Phase 3: entropy = -mean(log(density + 1e-9)) ----------------
__global__ void entropy_kernel(float* __restrict__ out) {
    __shared__ float red[1024];
    int t = threadIdx.x;
    float s = 0.f;
    for (int i = t; i < NROWS; i += 1024)
        s += logf(g_density[i] + 1e-9f);
    red[t] = s;
    __syncthreads();
    #pragma unroll
    for (int o = 512; o; o >>= 1) {
        if (t < o) red[t] += red[t + o];
        __syncthreads();
    }
    if (t == 0) out[0] = -red[0] / (float)NROWS;
}

// ---------------- launch ----------------
extern "C" void kernel_launch(void* const* d_in, const int* in_sizes, int n_in,
                              void* d_out, int out_size) {
    (void)in_sizes; (void)n_in; (void)out_size;
    const float* x = (const float*)d_in[0];
    float* out = (float*)d_out;

    cudaFuncSetAttribute(kde_sym_kernel,
                         cudaFuncAttributeMaxDynamicSharedMemorySize, SMEM_BYTES);

    normalize_kernel<<<NROWS / 8, 256>>>(x);
    kde_sym_kernel<<<NT, 256, SMEM_BYTES>>>();
    entropy_kernel<<<1, 1024>>>(out);
}

// round 5
// speedup vs baseline: 1.8667x; 1.2502x over previous
#include <cuda_runtime.h>
#include <cuda_bf16.h>
#include <cstdint>

#define NROWS 16384
#define DIM   256
#define NT    (NROWS / 128)        // 128 tiles per side
#define NPAIR (NT / 2)             // 64 pairs, 129 tiles each
#define NTILES 8256                // NT*(NT+1)/2
#define NCTA  296
#define LDSB  272                  // bytes per smem row (256 + 16 pad) -> conflict-free
#define KS    (5.0f / 256.0f)      // kappa folded with 16x16 quant scaling
#define TILE_SM_BYTES (128 * LDSB)             // 34816
#define SMEM_BYTES (3 * TILE_SM_BYTES)         // A + 2x B = 104448

// Scratch (device globals; no allocations allowed)
__device__ uint8_t g_xq[NROWS * DIM];   // normalized rows, e4m3, scaled by 16
__device__ float   g_density[NROWS];

// ---------------- Phase 1: L2-normalize rows -> e4m3 (x16); zero g_density ----------------
static __device__ __forceinline__ uint16_t pack_e4m3x2(float lo, float hi) {
    uint16_t r;
    asm("cvt.rn.satfinite.e4m3x2.f32 %0, %1, %2;" : "=h"(r) : "f"(hi), "f"(lo));
    return r;
}

__global__ void normalize_kernel(const float* __restrict__ x) {
    int gwarp = (blockIdx.x * blockDim.x + threadIdx.x) >> 5;
    int lane  = threadIdx.x & 31;
    if (gwarp >= NROWS) return;
    const float4* p = reinterpret_cast<const float4*>(x + (size_t)gwarp * DIM);
    float4 v0 = p[lane * 2 + 0];
    float4 v1 = p[lane * 2 + 1];
    float ss = v0.x*v0.x + v0.y*v0.y + v0.z*v0.z + v0.w*v0.w
             + v1.x*v1.x + v1.y*v1.y + v1.z*v1.z + v1.w*v1.w;
    #pragma unroll
    for (int o = 16; o; o >>= 1) ss += __shfl_xor_sync(0xffffffffu, ss, o);
    float inv = 16.0f / fmaxf(sqrtf(ss), 1e-12f);

    uint16_t b01 = pack_e4m3x2(v0.x * inv, v0.y * inv);
    uint16_t b23 = pack_e4m3x2(v0.z * inv, v0.w * inv);
    uint16_t b45 = pack_e4m3x2(v1.x * inv, v1.y * inv);
    uint16_t b67 = pack_e4m3x2(v1.z * inv, v1.w * inv);
    uint2 out;
    out.x = (uint32_t)b01 | ((uint32_t)b23 << 16);
    out.y = (uint32_t)b45 | ((uint32_t)b67 << 16);
    reinterpret_cast<uint2*>(g_xq)[gwarp * (DIM / 8) + lane] = out;
    if (lane == 0) g_density[gwarp] = 0.0f;
}

// ---------------- helpers ----------------
static __device__ __forceinline__ void ldsm_x4(uint32_t* r, uint32_t addr) {
    asm volatile("ldmatrix.sync.aligned.m8n8.x4.shared.b16 {%0,%1,%2,%3}, [%4];\n"
                 : "=r"(r[0]), "=r"(r[1]), "=r"(r[2]), "=r"(r[3]) : "r"(addr));
}
static __device__ __forceinline__ void mma_fp8(float* c, const uint32_t* a, const uint32_t* b) {
    asm volatile("mma.sync.aligned.m16n8k32.row.col.f32.e4m3.e4m3.f32 "
                 "{%0,%1,%2,%3}, {%4,%5,%6,%7}, {%8,%9}, {%0,%1,%2,%3};\n"
                 : "+f"(c[0]), "+f"(c[1]), "+f"(c[2]), "+f"(c[3])
                 : "r"(a[0]), "r"(a[1]), "r"(a[2]), "r"(a[3]),
                   "r"(b[0]), "r"(b[1]));
}
#define CP_ASYNC16(dst, src) \
    asm volatile("cp.async.cg.shared.global [%0], [%1], 16;" :: "r"(dst), "l"(src) : "memory")
#define CP_COMMIT()  asm volatile("cp.async.commit_group;" ::: "memory")
#define CP_WAIT0()   asm volatile("cp.async.wait_group 0;" :: : "memory")

// load a 128x256B fp8 tile (2048 x 16B, 8 per thread)
static __device__ __forceinline__ void load_tile(uint32_t dst_base, int grow0, int tid) {
    #pragma unroll
    for (int i = 0; i < 8; ++i) {
        int id = i * 256 + tid;
        int r = id >> 4, u = id & 15;
        uint32_t dst = dst_base + (uint32_t)(r * LDSB + u * 16);
        const char* src = (const char*)g_xq + (size_t)(grow0 + r) * DIM + u * 16;
        CP_ASYNC16(dst, src);
    }
}

// pair-ordered global tile index -> (ti, tj), ti <= tj
static __device__ __forceinline__ void tile_of(int q, int& ti, int& tj) {
    int p = q / 129, r = q - p * 129;
    int seg1 = NT - p;
    if (r < seg1) { ti = p;          tj = p + r; }
    else          { ti = NT - 1 - p; tj = NT - 1 - p + (r - seg1); }
}

// ---------------- Phase 2: persistent symmetric fused FP8 GEMM ----------------
__global__ void __launch_bounds__(256, 2) kde_sym_kernel() {
    extern __shared__ uint8_t sm[];
    uint32_t A_sm = (uint32_t)__cvta_generic_to_shared(sm);
    uint32_t B_sm = A_sm + TILE_SM_BYTES;

    int tid  = threadIdx.x;
    int lane = tid & 31;
    int wid  = tid >> 5;
    int warp_m = wid & 3;        // 32 rows each
    int warp_n = wid >> 2;       // 64 cols each

    int qbeg = (int)(((long long)blockIdx.x * NTILES) / NCTA);
    int qend = (int)(((long long)(blockIdx.x + 1) * NTILES) / NCTA);

    // ldmatrix byte addressing (same pattern as bf16, fp8 packs 2 per b16)
    int a_rb = (lane & 15) * LDSB + ((lane >> 4) * 16);
    int b_rb = ((lane & 7) + ((lane >> 4) << 3)) * LDSB + (((lane >> 3) & 1) * 16);

    int ti, tj;
    tile_of(qbeg, ti, tj);
    int cur_ti = ti;

    // prologue: A panel + first B tile
    load_tile(A_sm, ti * 128, tid);
    load_tile(B_sm, tj * 128, tid);
    CP_COMMIT();
    CP_WAIT0();
    __syncthreads();

    float rowacc[2][2] = {{0.f,0.f},{0.f,0.f}};
    int cur = 0;

    for (int q = qbeg; q < qend; ++q) {
        tile_of(q, ti, tj);
        bool diag = (ti == tj);

        // prefetch next B tile into other buffer
        int qn = q + 1;
        int nti = 0, ntj = 0;
        if (qn < qend) {
            tile_of(qn, nti, ntj);
            load_tile(B_sm + (cur ^ 1) * TILE_SM_BYTES, ntj * 128, tid);
            CP_COMMIT();
        }

        // ---- 8-kstep FP8 MMA mainloop ----
        float cfr[2][8][4];
        #pragma unroll
        for (int mf = 0; mf < 2; ++mf)
            #pragma unroll
            for (int nf = 0; nf < 8; ++nf)
                #pragma unroll
                for (int e = 0; e < 4; ++e) cfr[mf][nf][e] = 0.f;

        uint32_t Ab = A_sm + (uint32_t)(warp_m * 32 * LDSB);
        uint32_t Bb = B_sm + (uint32_t)(cur * TILE_SM_BYTES + warp_n * 64 * LDSB);
        #pragma unroll
        for (int ks = 0; ks < 8; ++ks) {
            int k0 = ks * 32;
            uint32_t a[2][4];
            #pragma unroll
            for (int mf = 0; mf < 2; ++mf)
                ldsm_x4(a[mf], Ab + (uint32_t)(mf * 16 * LDSB + a_rb + k0));
            uint32_t bfr[8][2];
            #pragma unroll
            for (int pp = 0; pp < 4; ++pp) {
                uint32_t t[4];
                ldsm_x4(t, Bb + (uint32_t)(pp * 16 * LDSB + b_rb + k0));
                bfr[2*pp][0]   = t[0]; bfr[2*pp][1]   = t[1];
                bfr[2*pp+1][0] = t[2]; bfr[2*pp+1][1] = t[3];
            }
            #pragma unroll
            for (int mf = 0; mf < 2; ++mf)
                #pragma unroll
                for (int nf = 0; nf < 8; ++nf)
                    mma_fp8(cfr[mf][nf], a[mf], bfr[nf]);
        }

        // ---- epilogue: exp, row sums (regs) + col sums (global atomics) ----
        float colacc[8][2];
        #pragma unroll
        for (int nf = 0; nf < 8; ++nf) { colacc[nf][0] = 0.f; colacc[nf][1] = 0.f; }

        #pragma unroll
        for (int mf = 0; mf < 2; ++mf)
            #pragma unroll
            for (int nf = 0; nf < 8; ++nf) {
                float e0 = __expf(KS * cfr[mf][nf][0]);
                float e1 = __expf(KS * cfr[mf][nf][1]);
                float e2 = __expf(KS * cfr[mf][nf][2]);
                float e3 = __expf(KS * cfr[mf][nf][3]);
                rowacc[mf][0] += e0 + e1;
                rowacc[mf][1] += e2 + e3;
                colacc[nf][0] += e0 + e2;
                colacc[nf][1] += e1 + e3;
            }

        if (!diag) {
            #pragma unroll
            for (int nf = 0; nf < 8; ++nf)
                #pragma unroll
                for (int hh = 0; hh < 2; ++hh) {
                    float s = colacc[nf][hh];
                    s += __shfl_xor_sync(0xffffffffu, s, 4);
                    s += __shfl_xor_sync(0xffffffffu, s, 8);
                    s += __shfl_xor_sync(0xffffffffu, s, 16);
                    if (lane < 4)
                        atomicAdd(&g_density[tj * 128 + warp_n * 64 + nf * 8 + 2 * lane + hh], s);
                }
        }

        // ---- buffer swap / A-panel boundary ----
        if (qn < qend && nti != cur_ti) {
            #pragma unroll
            for (int mf = 0; mf < 2; ++mf)
                #pragma unroll
                for (int rp = 0; rp < 2; ++rp) {
                    float s = rowacc[mf][rp];
                    s += __shfl_xor_sync(0xffffffffu, s, 1);
                    s += __shfl_xor_sync(0xffffffffu, s, 2);
                    if ((lane & 3) == 0)
                        atomicAdd(&g_density[cur_ti * 128 + warp_m * 32 + mf * 16 + rp * 8 + (lane >> 2)], s);
                    rowacc[mf][rp] = 0.f;
                }
            CP_WAIT0();
            __syncthreads();              // done with A before overwrite
            load_tile(A_sm, nti * 128, tid);
            CP_COMMIT();
            CP_WAIT0();
            __syncthreads();
            cur_ti = nti;
        } else {
            CP_WAIT0();
            __syncthreads();
        }
        cur ^= 1;
    }

    // final row-sum flush
    #pragma unroll
    for (int mf = 0; mf < 2; ++mf)
        #pragma unroll
        for (int rp = 0; rp < 2; ++rp) {
            float s = rowacc[mf][rp];
            s += __shfl_xor_sync(0xffffffffu, s, 1);
            s += __shfl_xor_sync(0xffffffffu, s, 2);
            if ((lane & 3) == 0)
                atomicAdd(&g_density[cur_ti * 128 + warp_m * 32 + mf * 16 + rp * 8 + (lane >> 2)], s);
        }
}

// ---------------- Phase 3: entropy = -mean(log(density + 1e-9)) ----------------
__global__ void entropy_kernel(float* __restrict__ out) {
    __shared__ float red[1024];
    int t = threadIdx.x;
    float s = 0.f;
    for (int i = t; i < NROWS; i += 1024)
        s += logf(g_density[i] + 1e-9f);
    red[t] = s;
    __syncthreads();
    #pragma unroll
    for (int o = 512; o; o >>= 1) {
        if (t < o) red[t] += red[t + o];
        __syncthreads();
    }
    if (t == 0) out[0] = -red[0] / (float)NROWS;
}

// ---------------- launch ----------------
extern "C" void kernel_launch(void* const* d_in, const int* in_sizes, int n_in,
                              void* d_out, int out_size) {
    (void)in_sizes; (void)n_in; (void)out_size;
    const float* x = (const float*)d_in[0];
    float* out = (float*)d_out;

    cudaFuncSetAttribute(kde_sym_kernel,
                         cudaFuncAttributeMaxDynamicSharedMemorySize, SMEM_BYTES);

    normalize_kernel<<<NROWS / 8, 256>>>(x);
    kde_sym_kernel<<<NCTA, 256, SMEM_BYTES>>>();
    entropy_kernel<<<1, 1024>>>(out);
}